// round 2
// baseline (speedup 1.0000x reference)
#include <cuda_runtime.h>

// Problem constants (fixed by setup_inputs)
#define NB        64
#define SD        52
#define CELLS     (SD * SD)      // 2704 = 338 * 8
#define CH        255
#define EPSF      1e-6f
#define IOU_T     0.7f
#define SCALE_IDX 2              // SCALES.index(52/13)
#define WPB       8              // warps (cells) per block
#define THREADS   (WPB * 32)

__global__ void zero_out_kernel(float* out) {
    int t = threadIdx.x;
    if (t < 257) out[t] = 0.0f;
}

__device__ __forceinline__ float warp_sum(float v) {
    #pragma unroll
    for (int o = 16; o > 0; o >>= 1) v += __shfl_down_sync(0xffffffffu, v, o);
    return v;
}

__global__ __launch_bounds__(THREADS, 5) void yolo_loss_kernel(
    const float* __restrict__ yhat,
    const float* __restrict__ ytru,
    const float* __restrict__ anchors,
    float* __restrict__ out)
{
    __shared__ float red[WPB][4];

    const int n    = blockIdx.y;
    const int wl   = threadIdx.x >> 5;          // warp in block
    const int lane = threadIdx.x & 31;
    const int cell = blockIdx.x * WPB + wl;     // 0..2703
    const int gi   = cell / SD;
    const int gj   = cell % SD;

    const size_t base = ((size_t)n * CELLS + cell) * CH;
    const float* Hb = yhat + base;
    const float* Yb = ytru + base;

    // ---- Gather box fields: channels {0..4, 85..89, 170..174} of each tensor.
    // lanes 0-14 load yhat fields, lanes 16-30 load y fields.
    int f = lane & 15;
    if (f > 14) f = 0;
    int ch = (f / 5) * 85 + (f % 5);
    float v = 0.0f;
    if (lane < 15)                 v = __ldg(Hb + ch);
    else if (lane >= 16 && lane < 31) v = __ldg(Yb + ch);

    const float invS = 1.0f / (float)SD;
    const float fj = (float)gj, fi = (float)gi;

    // Broadcast to all lanes; convert x,y to absolute centers.
    float hcx[3], hcy[3], hw[3], hh[3], hcf[3];
    float ycx[3], ycy[3], yw[3], yh[3], ycf[3];
    #pragma unroll
    for (int b = 0; b < 3; b++) {
        hcx[b] = (__shfl_sync(0xffffffffu, v, b * 5 + 0) + fj) * invS;
        hcy[b] = (__shfl_sync(0xffffffffu, v, b * 5 + 1) + fi) * invS;
        hw[b]  =  __shfl_sync(0xffffffffu, v, b * 5 + 2);
        hh[b]  =  __shfl_sync(0xffffffffu, v, b * 5 + 3);
        hcf[b] =  __shfl_sync(0xffffffffu, v, b * 5 + 4);
        ycx[b] = (__shfl_sync(0xffffffffu, v, 16 + b * 5 + 0) + fj) * invS;
        ycy[b] = (__shfl_sync(0xffffffffu, v, 16 + b * 5 + 1) + fi) * invS;
        yw[b]  =  __shfl_sync(0xffffffffu, v, 16 + b * 5 + 2);
        yh[b]  =  __shfl_sync(0xffffffffu, v, 16 + b * 5 + 3);
        ycf[b] =  __shfl_sync(0xffffffffu, v, 16 + b * 5 + 4);
    }

    // ---- IOU 3x3: per-pb max (noobj mask), per-tb argmax (responsible box).
    int   bestp[3];
    float bestv[3] = {-1.0f, -1.0f, -1.0f};
    float noobj[3];
    #pragma unroll
    for (int pb = 0; pb < 3; pb++) {
        float px1 = hcx[pb] - 0.5f * hw[pb], px2 = hcx[pb] + 0.5f * hw[pb];
        float py1 = hcy[pb] - 0.5f * hh[pb], py2 = hcy[pb] + 0.5f * hh[pb];
        float pa  = hw[pb] * hh[pb];
        float m = -1.0f;
        #pragma unroll
        for (int tb = 0; tb < 3; tb++) {
            float qx1 = ycx[tb] - 0.5f * yw[tb], qx2 = ycx[tb] + 0.5f * yw[tb];
            float qy1 = ycy[tb] - 0.5f * yh[tb], qy2 = ycy[tb] + 0.5f * yh[tb];
            float wi = fmaxf(fminf(px2, qx2) - fmaxf(px1, qx1), 0.0f);
            float hi = fmaxf(fminf(py2, qy2) - fmaxf(py1, qy1), 0.0f);
            float inter = wi * hi;
            float uni = pa + yw[tb] * yh[tb] - inter;
            float iou = inter / (uni + EPSF);
            m = fmaxf(m, iou);
            if (iou > bestv[tb]) { bestv[tb] = iou; bestp[tb] = pb; }
        }
        noobj[pb] = (m < IOU_T) ? 1.0f : 0.0f;
    }

    float ho[3];
    #pragma unroll
    for (int tb = 0; tb < 3; tb++) ho[tb] = (ycf[tb] > 0.0f) ? 1.0f : 0.0f;

    // ---- Scalar losses (lane 0 only; values identical on all lanes).
    float coordA = 0.0f, objA = 0.0f, noobjA = 0.0f;
    if (lane == 0) {
        const float* anc = anchors + SCALE_IDX * 6;
        #pragma unroll
        for (int tb = 0; tb < 3; tb++) {
            int pb = bestp[tb];
            float dx = (hcx[pb] - ycx[tb]) * (float)SD;   // == hx[pb]-yx[tb]
            float dy = (hcy[pb] - ycy[tb]) * (float)SD;
            float aw_p = __ldg(anc + pb * 2), ah_p = __ldg(anc + pb * 2 + 1);
            float aw_t = __ldg(anc + tb * 2), ah_t = __ldg(anc + tb * 2 + 1);
            float dlw = __logf(hw[pb] / aw_p + EPSF) - __logf(yw[tb] / aw_t + EPSF);
            float dlh = __logf(hh[pb] / ah_p + EPSF) - __logf(yh[tb] / ah_t + EPSF);
            float c = dx * dx + dy * dy + dlw * dlw + dlh * dlh;
            coordA += c * ho[tb] * (2.0f - yw[tb] * yh[tb]);   // SCALE_COORD
            float dcf = hcf[pb] - ycf[tb];
            objA += dcf * dcf * ho[tb];
            noobjA += hcf[tb] * hcf[tb] * noobj[tb];           // NO_OBJ_V3
        }
    }

    // ---- Class loss: stream 3x80 channels per tensor straight from global.
    float clsA = 0.0f;
    #pragma unroll
    for (int tb = 0; tb < 3; tb++) {
        const float* Yc = Yb + tb * 85 + 5;
        const float* Hc = Hb + bestp[tb] * 85 + 5;
        float d0 = __ldg(Hc + lane)      - __ldg(Yc + lane);
        float d1 = __ldg(Hc + lane + 32) - __ldg(Yc + lane + 32);
        float s = d0 * d0 + d1 * d1;
        if (lane < 16) {
            float d2 = __ldg(Hc + lane + 64) - __ldg(Yc + lane + 64);
            s += d2 * d2;
        }
        clsA += s * ho[tb];
    }
    clsA = warp_sum(clsA);

    // ---- Block reduction + atomics (all cells in block share image n).
    if (lane == 0) {
        red[wl][0] = coordA; red[wl][1] = clsA;
        red[wl][2] = noobjA; red[wl][3] = objA;
    }
    __syncthreads();
    if (threadIdx.x < 4) {
        float s = 0.0f;
        #pragma unroll
        for (int w = 0; w < WPB; w++) s += red[w][threadIdx.x];
        // layout: coord[0:64) class[64:128) noobj[128:192) obj[192:256) prior[256]
        atomicAdd(out + threadIdx.x * NB + n, s);
    }
}

extern "C" void kernel_launch(void* const* d_in, const int* in_sizes, int n_in,
                              void* d_out, int out_size) {
    const float* yhat    = (const float*)d_in[0];
    const float* y       = (const float*)d_in[1];
    const float* anchors = (const float*)d_in[2];
    float* out = (float*)d_out;

    zero_out_kernel<<<1, 288>>>(out);
    dim3 grid(CELLS / WPB, NB);   // (338, 64)
    yolo_loss_kernel<<<grid, THREADS>>>(yhat, y, anchors, out);
}

// round 3
// speedup vs baseline: 1.2330x; 1.2330x over previous
#include <cuda_runtime.h>

// Problem constants (fixed by setup_inputs)
#define NB        64
#define SD        52
#define CELLS     (SD * SD)          // 2704
#define CH        255
#define CPB       16                 // cells per tile
#define NTILES    (NB * CELLS / CPB) // 64 * 169 = 10816
#define TILEF     (CPB * CH)         // 4080 floats
#define TILEF4    (TILEF / 4)        // 1020 float4
#define THREADS   256
#define TPC       16                 // threads per cell
#define GRID      444                // 3 blocks/SM * 148
#define EPSF      1e-6f
#define IOU_T     0.7f
#define SCALE_IDX 2

__global__ void zero_out_kernel(float* out) {
    int t = threadIdx.x;
    if (t < 257) out[t] = 0.0f;
}

__device__ __forceinline__ float warp_sum(float v) {
    #pragma unroll
    for (int o = 16; o > 0; o >>= 1) v += __shfl_down_sync(0xffffffffu, v, o);
    return v;
}

__device__ __forceinline__ void prefetch_tile(const float* __restrict__ gH,
                                              const float* __restrict__ gY,
                                              float* sH, float* sY, int tid) {
    unsigned dH = (unsigned)__cvta_generic_to_shared(sH);
    unsigned dY = (unsigned)__cvta_generic_to_shared(sY);
    #pragma unroll 4
    for (int i = tid; i < TILEF4; i += THREADS) {
        asm volatile("cp.async.cg.shared.global [%0], [%1], 16;\n"
                     :: "r"(dH + i * 16), "l"(gH + i * 4));
        asm volatile("cp.async.cg.shared.global [%0], [%1], 16;\n"
                     :: "r"(dY + i * 16), "l"(gY + i * 4));
    }
}

__global__ __launch_bounds__(THREADS) void yolo_loss_kernel(
    const float* __restrict__ yhat,
    const float* __restrict__ ytru,
    const float* __restrict__ anchors,
    float* __restrict__ out)
{
    extern __shared__ float smem[];          // [2 bufs][H|Y][TILEF]
    __shared__ float red[8][4];

    const int tid = threadIdx.x;
    float* bufH[2] = { smem,             smem + 2 * TILEF };
    float* bufY[2] = { smem + TILEF,     smem + 3 * TILEF };

    int t0 = blockIdx.x;
    if (t0 < NTILES) {
        size_t g = (size_t)t0 * TILEF;
        prefetch_tile(yhat + g, ytru + g, bufH[0], bufY[0], tid);
    }
    asm volatile("cp.async.commit_group;\n" ::: "memory");

    int buf = 0;
    for (int t = t0; t < NTILES; t += GRID) {
        // Prefetch next tile into the other buffer, then wait for current.
        int tn = t + GRID;
        if (tn < NTILES) {
            size_t g = (size_t)tn * TILEF;
            prefetch_tile(yhat + g, ytru + g, bufH[buf ^ 1], bufY[buf ^ 1], tid);
        }
        asm volatile("cp.async.commit_group;\n" ::: "memory");
        asm volatile("cp.async.wait_group 1;\n" ::: "memory");
        __syncthreads();

        // ---- Compute on current tile ----
        const int n     = t / (CELLS / CPB);
        const int cell0 = (t % (CELLS / CPB)) * CPB;
        const int lc    = tid / TPC;
        const int sub   = tid % TPC;
        const int cellIdx = cell0 + lc;
        const int gi = cellIdx / SD;
        const int gj = cellIdx % SD;

        const float* H = bufH[buf] + lc * CH;
        const float* Y = bufY[buf] + lc * CH;

        float hx[3], hy[3], hw[3], hh[3], hc[3];
        float yx[3], yy[3], yw[3], yh[3], yc[3];
        #pragma unroll
        for (int b = 0; b < 3; b++) {
            const float* hb = H + b * 85;
            const float* yb = Y + b * 85;
            hx[b] = hb[0]; hy[b] = hb[1]; hw[b] = hb[2]; hh[b] = hb[3]; hc[b] = hb[4];
            yx[b] = yb[0]; yy[b] = yb[1]; yw[b] = yb[2]; yh[b] = yb[3]; yc[b] = yb[4];
        }

        const float invS = 1.0f / (float)SD;
        const float fj = (float)gj, fi = (float)gi;

        float hx1[3], hx2[3], hy1[3], hy2[3];
        float tx1[3], tx2[3], ty1[3], ty2[3];
        #pragma unroll
        for (int b = 0; b < 3; b++) {
            float cx = (hx[b] + fj) * invS, cy = (hy[b] + fi) * invS;
            hx1[b] = cx - 0.5f * hw[b]; hx2[b] = cx + 0.5f * hw[b];
            hy1[b] = cy - 0.5f * hh[b]; hy2[b] = cy + 0.5f * hh[b];
            cx = (yx[b] + fj) * invS; cy = (yy[b] + fi) * invS;
            tx1[b] = cx - 0.5f * yw[b]; tx2[b] = cx + 0.5f * yw[b];
            ty1[b] = cy - 0.5f * yh[b]; ty2[b] = cy + 0.5f * yh[b];
        }

        int   idx_t[3];
        float best_t[3] = {-1.0f, -1.0f, -1.0f};
        float noobj_f[3];
        #pragma unroll
        for (int pb = 0; pb < 3; pb++) {
            float pa = hw[pb] * hh[pb];
            float m = -1.0f;
            #pragma unroll
            for (int tb = 0; tb < 3; tb++) {
                float wi = fmaxf(fminf(hx2[pb], tx2[tb]) - fmaxf(hx1[pb], tx1[tb]), 0.0f);
                float hi = fmaxf(fminf(hy2[pb], ty2[tb]) - fmaxf(hy1[pb], ty1[tb]), 0.0f);
                float inter = wi * hi;
                float uni = pa + yw[tb] * yh[tb] - inter;
                float iou = inter / (uni + EPSF);
                m = fmaxf(m, iou);
                if (iou > best_t[tb]) { best_t[tb] = iou; idx_t[tb] = pb; }
            }
            noobj_f[pb] = (m < IOU_T) ? 1.0f : 0.0f;
        }

        float coord_acc = 0.0f, cls_acc = 0.0f, noobj_acc = 0.0f, obj_acc = 0.0f;

        if (sub == 0) {
            const float* anc = anchors + SCALE_IDX * 6;
            #pragma unroll
            for (int tb = 0; tb < 3; tb++) {
                int pb = idx_t[tb];
                float ho = (yc[tb] > 0.0f) ? 1.0f : 0.0f;
                float aw_p = __ldg(anc + pb * 2), ah_p = __ldg(anc + pb * 2 + 1);
                float aw_t = __ldg(anc + tb * 2), ah_t = __ldg(anc + tb * 2 + 1);
                float dx = hx[pb] - yx[tb];
                float dy = hy[pb] - yy[tb];
                float dlw = __logf(hw[pb] / aw_p + EPSF) - __logf(yw[tb] / aw_t + EPSF);
                float dlh = __logf(hh[pb] / ah_p + EPSF) - __logf(yh[tb] / ah_t + EPSF);
                float c = dx * dx + dy * dy + dlw * dlw + dlh * dlh;
                coord_acc += c * ho * (2.0f - yw[tb] * yh[tb]);   // SCALE_COORD
                float dc = hc[pb] - yc[tb];
                obj_acc += dc * dc * ho;
                noobj_acc += hc[tb] * hc[tb] * noobj_f[tb];        // NO_OBJ_V3
            }
        }

        // Class loss: 3 tb x 80 classes split across 16 threads (5 iters each)
        #pragma unroll
        for (int tb = 0; tb < 3; tb++) {
            int pb = idx_t[tb];
            float ho = (yc[tb] > 0.0f) ? 1.0f : 0.0f;
            const float* Hc = H + pb * 85 + 5;
            const float* Yc = Y + tb * 85 + 5;
            float s = 0.0f;
            #pragma unroll
            for (int c = sub; c < 80; c += TPC) {
                float d = Hc[c] - Yc[c];
                s += d * d;
            }
            cls_acc += s * ho;
        }

        coord_acc = warp_sum(coord_acc);
        cls_acc   = warp_sum(cls_acc);
        noobj_acc = warp_sum(noobj_acc);
        obj_acc   = warp_sum(obj_acc);

        const int wid = tid >> 5;
        if ((tid & 31) == 0) {
            red[wid][0] = coord_acc;
            red[wid][1] = cls_acc;
            red[wid][2] = noobj_acc;
            red[wid][3] = obj_acc;
        }
        __syncthreads();
        if (tid < 4) {
            float s = 0.0f;
            #pragma unroll
            for (int w = 0; w < 8; w++) s += red[w][tid];
            atomicAdd(out + tid * NB + n, s);
        }
        __syncthreads();   // buffers + red[] reusable next iteration
        buf ^= 1;
    }
}

extern "C" void kernel_launch(void* const* d_in, const int* in_sizes, int n_in,
                              void* d_out, int out_size) {
    const float* yhat    = (const float*)d_in[0];
    const float* y       = (const float*)d_in[1];
    const float* anchors = (const float*)d_in[2];
    float* out = (float*)d_out;

    static_assert(4 * TILEF * sizeof(float) == 65280, "smem layout");
    cudaFuncSetAttribute(yolo_loss_kernel,
                         cudaFuncAttributeMaxDynamicSharedMemorySize, 65280);

    zero_out_kernel<<<1, 288>>>(out);
    yolo_loss_kernel<<<GRID, THREADS, 65280>>>(yhat, y, anchors, out);
}

// round 4
// speedup vs baseline: 1.3521x; 1.0966x over previous
#include <cuda_runtime.h>

// Problem constants (fixed by setup_inputs)
#define NB        64
#define SD        52
#define CELLS     (SD * SD)            // 2704
#define CH        255
#define QCELLS    4                    // cells per quad (alignment unit)
#define QF        (QCELLS * CH)        // 1020 floats per tensor per quad
#define QF4       (QF / 4)             // 255 float4
#define NQUADS    (NB * CELLS / QCELLS)// 43264
#define WPB       4                    // warps per block
#define THREADS   (WPB * 32)
#define EPSF      1e-6f
#define IOU_T     0.7f
#define SCALE_IDX 2

__global__ void zero_out_kernel(float* out) {
    int t = threadIdx.x;
    if (t < 257) out[t] = 0.0f;
}

__device__ __forceinline__ float warp_sum(float v) {
    #pragma unroll
    for (int o = 16; o > 0; o >>= 1) v += __shfl_down_sync(0xffffffffu, v, o);
    return v;
}

__global__ __launch_bounds__(THREADS, 6) void yolo_loss_kernel(
    const float* __restrict__ yhat,
    const float* __restrict__ ytru,
    const float* __restrict__ anchors,
    float* __restrict__ out)
{
    // Per-warp private staging: [H 1020 | Y 1020] floats. No cross-warp sharing.
    __shared__ float smem[WPB * 2 * QF];

    const int wl   = threadIdx.x >> 5;
    const int lane = threadIdx.x & 31;
    const int quad = blockIdx.x * WPB + wl;          // 0..43263
    const int n    = quad / (CELLS / QCELLS);        // image
    const int c0   = (quad % (CELLS / QCELLS)) * QCELLS;

    float* sH = smem + wl * 2 * QF;
    float* sY = sH + QF;

    // ---- Stage quad: 255 float4 per tensor, LDG.128 -> STS.128, warp-private.
    {
        const float4* gH = reinterpret_cast<const float4*>(yhat + (size_t)quad * QF);
        const float4* gY = reinterpret_cast<const float4*>(ytru + (size_t)quad * QF);
        float4* dH = reinterpret_cast<float4*>(sH);
        float4* dY = reinterpret_cast<float4*>(sY);
        // two batches of 4 iters: <=32 regs of load data in flight, MLP 8/lane
        #pragma unroll
        for (int half = 0; half < 2; half++) {
            float4 h[4], y[4];
            #pragma unroll
            for (int k = 0; k < 4; k++) {
                int i = lane + (half * 4 + k) * 32;
                if (i < QF4) { h[k] = gH[i]; y[k] = gY[i]; }
            }
            #pragma unroll
            for (int k = 0; k < 4; k++) {
                int i = lane + (half * 4 + k) * 32;
                if (i < QF4) { dH[i] = h[k]; dY[i] = y[k]; }
            }
        }
    }
    __syncwarp();

    // ---- Compute: 8 lanes per cell, 4 cells per warp.
    const int g   = lane >> 3;       // cell within quad
    const int sub = lane & 7;
    const int cellIdx = c0 + g;
    const int gi = cellIdx / SD;
    const int gj = cellIdx % SD;

    const float* H = sH + g * CH;
    const float* Y = sY + g * CH;

    float hx[3], hy[3], hw[3], hh[3], hc[3];
    float yx[3], yy[3], yw[3], yh[3], yc[3];
    #pragma unroll
    for (int b = 0; b < 3; b++) {
        const float* hb = H + b * 85;
        const float* yb = Y + b * 85;
        hx[b] = hb[0]; hy[b] = hb[1]; hw[b] = hb[2]; hh[b] = hb[3]; hc[b] = hb[4];
        yx[b] = yb[0]; yy[b] = yb[1]; yw[b] = yb[2]; yh[b] = yb[3]; yc[b] = yb[4];
    }

    const float invS = 1.0f / (float)SD;
    const float fj = (float)gj, fi = (float)gi;

    float hx1[3], hx2[3], hy1[3], hy2[3];
    float tx1[3], tx2[3], ty1[3], ty2[3];
    #pragma unroll
    for (int b = 0; b < 3; b++) {
        float cx = (hx[b] + fj) * invS, cy = (hy[b] + fi) * invS;
        hx1[b] = cx - 0.5f * hw[b]; hx2[b] = cx + 0.5f * hw[b];
        hy1[b] = cy - 0.5f * hh[b]; hy2[b] = cy + 0.5f * hh[b];
        cx = (yx[b] + fj) * invS; cy = (yy[b] + fi) * invS;
        tx1[b] = cx - 0.5f * yw[b]; tx2[b] = cx + 0.5f * yw[b];
        ty1[b] = cy - 0.5f * yh[b]; ty2[b] = cy + 0.5f * yh[b];
    }

    // IOU 3x3: per-pb max (noobj), per-tb argmax (responsible predictor).
    int   idx_t[3];
    float best_t[3] = {-1.0f, -1.0f, -1.0f};
    float noobj_f[3];
    #pragma unroll
    for (int pb = 0; pb < 3; pb++) {
        float pa = hw[pb] * hh[pb];
        float m = -1.0f;
        #pragma unroll
        for (int tb = 0; tb < 3; tb++) {
            float wi = fmaxf(fminf(hx2[pb], tx2[tb]) - fmaxf(hx1[pb], tx1[tb]), 0.0f);
            float hi = fmaxf(fminf(hy2[pb], ty2[tb]) - fmaxf(hy1[pb], ty1[tb]), 0.0f);
            float inter = wi * hi;
            float uni = pa + yw[tb] * yh[tb] - inter;
            float iou = inter / (uni + EPSF);
            m = fmaxf(m, iou);
            if (iou > best_t[tb]) { best_t[tb] = iou; idx_t[tb] = pb; }
        }
        noobj_f[pb] = (m < IOU_T) ? 1.0f : 0.0f;
    }

    float coord_acc = 0.0f, cls_acc = 0.0f, noobj_acc = 0.0f, obj_acc = 0.0f;

    if (sub == 0) {
        const float* anc = anchors + SCALE_IDX * 6;
        #pragma unroll
        for (int tb = 0; tb < 3; tb++) {
            int pb = idx_t[tb];
            float ho = (yc[tb] > 0.0f) ? 1.0f : 0.0f;
            float aw_p = __ldg(anc + pb * 2), ah_p = __ldg(anc + pb * 2 + 1);
            float aw_t = __ldg(anc + tb * 2), ah_t = __ldg(anc + tb * 2 + 1);
            float dx = hx[pb] - yx[tb];
            float dy = hy[pb] - yy[tb];
            float dlw = __logf(hw[pb] / aw_p + EPSF) - __logf(yw[tb] / aw_t + EPSF);
            float dlh = __logf(hh[pb] / ah_p + EPSF) - __logf(yh[tb] / ah_t + EPSF);
            float c = dx * dx + dy * dy + dlw * dlw + dlh * dlh;
            coord_acc += c * ho * (2.0f - yw[tb] * yh[tb]);   // SCALE_COORD
            float dc = hc[pb] - yc[tb];
            obj_acc += dc * dc * ho;
            noobj_acc += hc[tb] * hc[tb] * noobj_f[tb];        // NO_OBJ_V3
        }
    }

    // Class loss: 3 tb x 80 classes split across 8 lanes (10 iters each)
    #pragma unroll
    for (int tb = 0; tb < 3; tb++) {
        int pb = idx_t[tb];
        float ho = (yc[tb] > 0.0f) ? 1.0f : 0.0f;
        const float* Hc = H + pb * 85 + 5;
        const float* Yc = Y + tb * 85 + 5;
        float s = 0.0f;
        #pragma unroll
        for (int c = sub; c < 80; c += 8) {
            float d = Hc[c] - Yc[c];
            s += d * d;
        }
        cls_acc += s * ho;
    }

    // ---- Warp reduction + per-warp atomics (all 4 cells share image n).
    coord_acc = warp_sum(coord_acc);
    cls_acc   = warp_sum(cls_acc);
    noobj_acc = warp_sum(noobj_acc);
    obj_acc   = warp_sum(obj_acc);

    if (lane == 0) {
        // layout: coord[0:64) class[64:128) noobj[128:192) obj[192:256) prior[256]
        atomicAdd(out + 0 * NB + n, coord_acc);
        atomicAdd(out + 1 * NB + n, cls_acc);
        atomicAdd(out + 2 * NB + n, noobj_acc);
        atomicAdd(out + 3 * NB + n, obj_acc);
    }
}

extern "C" void kernel_launch(void* const* d_in, const int* in_sizes, int n_in,
                              void* d_out, int out_size) {
    const float* yhat    = (const float*)d_in[0];
    const float* y       = (const float*)d_in[1];
    const float* anchors = (const float*)d_in[2];
    float* out = (float*)d_out;

    zero_out_kernel<<<1, 288>>>(out);
    yolo_loss_kernel<<<NQUADS / WPB, THREADS>>>(yhat, y, anchors, out);  // 10816 blocks
}